// round 16
// baseline (speedup 1.0000x reference)
#include <cuda_runtime.h>
#include <cuda_bf16.h>
#include <cstdint>

// QuantizedCodebook: inputs [32,4096,64] f32, codebook [1024,64] f32.
// Output (f32 concat): [ loss(1) | z_q(N*64) | indices-as-f32(N) ]
//
// R16 = R15 (best, 236us; occ3/regs80) pushed to __launch_bounds__(256,4):
// 64-reg target -> 32 warps/SM. Math identical: bf16 split B'=[ch|cl],
// afh*ch + afl*ch + afh*cl, |err|~1e-4; top-3 + exact fp32 rescore within
// MARGIN; exact z_q/loss epilogue.

#define D 64
#define KCODES 1024
#define TPB 256
#define ROWS_PER_CTA 128
#define CHUNK_N 64
#define NCHUNKS (KCODES / CHUNK_N)       // 16
#define NK 4                             // 4 k16-steps per 64-dim plane
#define RSA 272                          // A row: [xh 128B | xl 128B] + 16 pad
#define RSB 272                          // B row: [ch 128B | cl 128B] + 16 pad
#define MARGIN 2e-3f

// dynamic smem layout (A-stage overlaps B0+B1 exactly: 128*272 = 34816)
#define SM_B0 0                          // 64*272 = 17408
#define SM_B1 17408
#define SM_CS 34816                      // csqr[1024] (4096)
#define SM_TS 38912                      // float top3 s [128][3] (1536)
#define SM_TI 40448                      // int   top3 i [128][3] (1536)
#define SMEM_TOTAL 41984

__device__ double g_loss_accum;
__device__ unsigned int g_ticket;
__device__ float g_csqr[KCODES];
__device__ unsigned int g_cbq[KCODES * 64];   // per code: [ch 32 u32 | cl 32 u32]

// ---------------- helpers ----------------
__device__ __forceinline__ uint32_t smem_u32(const void* p) {
    uint32_t a;
    asm("{ .reg .u64 t; cvta.to.shared.u64 t, %1; cvt.u32.u64 %0, t; }"
        : "=r"(a) : "l"(p));
    return a;
}
__device__ __forceinline__ uint32_t packbf(float a, float b) {
    uint32_t r;
    asm("cvt.rn.bf16x2.f32 %0, %1, %2;" : "=r"(r) : "f"(b), "f"(a));
    return r;
}
__device__ __forceinline__ float lo_f(uint32_t p) { return __uint_as_float(p << 16); }
__device__ __forceinline__ float hi_f(uint32_t p) { return __uint_as_float(p & 0xffff0000u); }

__device__ __forceinline__ void ldsm4(uint32_t& r0, uint32_t& r1,
                                      uint32_t& r2, uint32_t& r3, uint32_t a) {
    asm volatile("ldmatrix.sync.aligned.m8n8.x4.shared.b16 {%0,%1,%2,%3}, [%4];"
                 : "=r"(r0), "=r"(r1), "=r"(r2), "=r"(r3) : "r"(a));
}
__device__ __forceinline__ void mma16816(float& c0, float& c1, float& c2, float& c3,
                                         uint32_t a0, uint32_t a1, uint32_t a2,
                                         uint32_t a3, uint32_t b0, uint32_t b1) {
    asm("mma.sync.aligned.m16n8k16.row.col.f32.bf16.bf16.f32 "
        "{%0,%1,%2,%3}, {%4,%5,%6,%7}, {%8,%9}, {%0,%1,%2,%3};"
        : "+f"(c0), "+f"(c1), "+f"(c2), "+f"(c3)
        : "r"(a0), "r"(a1), "r"(a2), "r"(a3), "r"(b0), "r"(b1));
}
__device__ __forceinline__ void cpa16(uint32_t dst, const void* src) {
    asm volatile("cp.async.cg.shared.global [%0], [%1], 16;"
                 :: "r"(dst), "l"(src));
}
#define CP_COMMIT() asm volatile("cp.async.commit_group;" ::: "memory")
#define CP_WAIT0()  asm volatile("cp.async.wait_group 0;" ::: "memory")

__device__ __forceinline__ void ins3(float s, int idx,
                                     float& s1, int& i1, float& s2, int& i2,
                                     float& s3, int& i3) {
    if (s < s3) {
        if (s < s2) {
            if (s < s1) { s3 = s2; i3 = i2; s2 = s1; i2 = i1; s1 = s; i1 = idx; }
            else        { s3 = s2; i3 = i2; s2 = s;  i2 = idx; }
        } else { s3 = s; i3 = idx; }
    }
}

// ---------------- kernel 1: prep (split codebook + norms) ----------------
__global__ void vq_prep_kernel(const float* __restrict__ codebook) {
    int j = blockIdx.x * blockDim.x + threadIdx.x;
    if (j == 0) { g_loss_accum = 0.0; g_ticket = 0u; }
    if (j >= KCODES) return;
    const float4* c4 = (const float4*)(codebook + (size_t)j * D);
    unsigned int* q = g_cbq + (size_t)j * 64;
    float s = 0.0f;
    #pragma unroll
    for (int i = 0; i < 16; i++) {
        float4 v = c4[i];
        s += v.x * v.x + v.y * v.y + v.z * v.z + v.w * v.w;
        uint32_t h0 = packbf(v.x, v.y), h1 = packbf(v.z, v.w);
        uint32_t l0 = packbf(v.x - lo_f(h0), v.y - hi_f(h0));
        uint32_t l1 = packbf(v.z - lo_f(h1), v.w - hi_f(h1));
        q[2 * i] = h0;       q[2 * i + 1] = h1;        // ch plane
        q[32 + 2 * i] = l0;  q[32 + 2 * i + 1] = l1;   // cl plane
    }
    g_csqr[j] = s;
}

__device__ __forceinline__ float exact_score(const float4* x4,
                                             const float* __restrict__ cb, int j) {
    const float4* c4 = (const float4*)(cb + (size_t)j * D);
    float dot = 0.0f;
    #pragma unroll
    for (int i = 0; i < 16; i++) {
        float4 a = x4[i], b = c4[i];
        dot += a.x * b.x + a.y * b.y + a.z * b.z + a.w * b.w;
    }
    return fmaf(-2.0f, dot, g_csqr[j]);
}

// ---------------- kernel 2: main ----------------
__global__ void __launch_bounds__(TPB, 4)
vq_main_kernel(const float* __restrict__ inp,
               const float* __restrict__ codebook,
               float* __restrict__ out, int n_rows) {
    extern __shared__ char dsm[];
    const uint32_t sbase = smem_u32(dsm);
    float* s_csqr = (float*)(dsm + SM_CS);
    float* s_ts = (float*)(dsm + SM_TS);
    int*   s_ti = (int*)(dsm + SM_TI);

    const int tid = threadIdx.x;
    const int l = tid & 31;
    const int w = tid >> 5;
    const int row0 = blockIdx.x * ROWS_PER_CTA;

    // ---- stage A [128 rows][xh|xl] bf16 stride 272 (overlaps B0+B1) ----
    if (tid < ROWS_PER_CTA) {
        const float4* xr = (const float4*)(inp + (size_t)(row0 + tid) * D);
        uint32_t* arow = (uint32_t*)(dsm + tid * RSA);
        #pragma unroll
        for (int i = 0; i < 16; i++) {
            float4 v = xr[i];
            uint32_t h0 = packbf(v.x, v.y), h1 = packbf(v.z, v.w);
            uint32_t l0 = packbf(v.x - lo_f(h0), v.y - hi_f(h0));
            uint32_t l1 = packbf(v.z - lo_f(h1), v.w - hi_f(h1));
            arow[2 * i] = h0;       arow[2 * i + 1] = h1;       // xh
            arow[32 + 2 * i] = l0;  arow[32 + 2 * i + 1] = l1;  // xl
        }
    }
    for (int g = tid; g < KCODES; g += TPB) s_csqr[g] = g_csqr[g];
    __syncthreads();

    // ---- preload A fragments (held all kernel): 4 k-steps x (hi, lo) ----
    uint32_t afh[NK][4], afl[NK][4];
    {
        uint32_t aoff = (uint32_t)((w * 16 + (l & 15)) * RSA + ((l & 16) ? 16 : 0));
        #pragma unroll
        for (int k = 0; k < NK; k++) {
            ldsm4(afh[k][0], afh[k][1], afh[k][2], afh[k][3], sbase + aoff + k * 32);
            ldsm4(afl[k][0], afl[k][1], afl[k][2], afl[k][3],
                  sbase + aoff + 128 + k * 32);
        }
    }
    __syncthreads();   // all A reads done before B overwrites the buffer

    float sA1 = 3.4e38f, sA2 = 3.4e38f, sA3 = 3.4e38f;
    float sB1 = 3.4e38f, sB2 = 3.4e38f, sB3 = 3.4e38f;
    int iA1 = 0, iA2 = 0, iA3 = 0, iB1 = 0, iB2 = 0, iB3 = 0;

    const uint32_t boff = (uint32_t)(((l & 7) + ((l & 16) ? 8 : 0)) * RSB
                                     + ((l & 8) ? 16 : 0));
    const int q2 = 2 * (l & 3);
    const uint4* cbq4 = (const uint4*)g_cbq;
    const uint32_t bb[2] = { sbase + SM_B0, sbase + SM_B1 };

    // staging: thread t stages row t>>2, uint4 cols (t&3)*4 .. +3
    const int st_row = tid >> 2;              // 0..63
    const int st_c0 = (tid & 3) * 4;          // 0,4,8,12

    // prefetch chunk 0: 64 codes x 256B = 1024 x 16B (4 per thread)
    {
        const uint4* src = cbq4 + (size_t)st_row * 16 + st_c0;
        uint32_t dst = bb[0] + (uint32_t)(st_row * RSB + st_c0 * 16);
        #pragma unroll
        for (int i = 0; i < 4; i++) cpa16(dst + i * 16, src + i);
        CP_COMMIT();
    }

    for (int t = 0; t < NCHUNKS; t++) {
        CP_WAIT0();
        __syncthreads();   // chunk t visible; all reads of other buf done
        if (t + 1 < NCHUNKS) {
            const uint4* src = cbq4 + (size_t)(t + 1) * CHUNK_N * 16
                             + (size_t)st_row * 16 + st_c0;
            uint32_t dst = bb[(t + 1) & 1]
                         + (uint32_t)(st_row * RSB + st_c0 * 16);
            #pragma unroll
            for (int i = 0; i < 4; i++) cpa16(dst + i * 16, src + i);
            CP_COMMIT();
        }
        const uint32_t bch = bb[t & 1];

        #pragma unroll
        for (int pair = 0; pair < 2; pair++) {
            // 2 n16 tiles (32 codes); 4 dst chains x depth 12
            float a0 = 0.f, a1 = 0.f, a2 = 0.f, a3 = 0.f;       // tile0 n8-lo
            float a4 = 0.f, a5 = 0.f, a6 = 0.f, a7 = 0.f;       // tile0 n8-hi
            float a8 = 0.f, a9 = 0.f, a10 = 0.f, a11 = 0.f;     // tile1 n8-lo
            float a12 = 0.f, a13 = 0.f, a14 = 0.f, a15 = 0.f;   // tile1 n8-hi
            uint32_t b0base = bch + (uint32_t)((2 * pair) * 16 * RSB) + boff;
            uint32_t b1base = b0base + (uint32_t)(16 * RSB);
            #pragma unroll
            for (int k = 0; k < NK; k++) {
                // tile 0 first (8 live B regs), then tile 1 — low reg peak
                {
                    uint32_t p0, p1, p2, p3, pc0, pc1, pc2, pc3;
                    ldsm4(p0, p1, p2, p3, b0base + k * 32);           // t0 ch
                    ldsm4(pc0, pc1, pc2, pc3, b0base + 128 + k * 32); // t0 cl
                    mma16816(a0, a1, a2, a3, afh[k][0], afh[k][1], afh[k][2], afh[k][3], p0, p1);
                    mma16816(a4, a5, a6, a7, afh[k][0], afh[k][1], afh[k][2], afh[k][3], p2, p3);
                    mma16816(a0, a1, a2, a3, afl[k][0], afl[k][1], afl[k][2], afl[k][3], p0, p1);
                    mma16816(a4, a5, a6, a7, afl[k][0], afl[k][1], afl[k][2], afl[k][3], p2, p3);
                    mma16816(a0, a1, a2, a3, afh[k][0], afh[k][1], afh[k][2], afh[k][3], pc0, pc1);
                    mma16816(a4, a5, a6, a7, afh[k][0], afh[k][1], afh[k][2], afh[k][3], pc2, pc3);
                }
                {
                    uint32_t q0, q1, q2r, q3, qc0, qc1, qc2, qc3;
                    ldsm4(q0, q1, q2r, q3, b1base + k * 32);          // t1 ch
                    ldsm4(qc0, qc1, qc2, qc3, b1base + 128 + k * 32); // t1 cl
                    mma16816(a8, a9, a10, a11, afh[k][0], afh[k][1], afh[k][2], afh[k][3], q0, q1);
                    mma16816(a12, a13, a14, a15, afh[k][0], afh[k][1], afh[k][2], afh[k][3], q2r, q3);
                    mma16816(a8, a9, a10, a11, afl[k][0], afl[k][1], afl[k][2], afl[k][3], q0, q1);
                    mma16816(a12, a13, a14, a15, afl[k][0], afl[k][1], afl[k][2], afl[k][3], q2r, q3);
                    mma16816(a8, a9, a10, a11, afh[k][0], afh[k][1], afh[k][2], afh[k][3], qc0, qc1);
                    mma16816(a12, a13, a14, a15, afh[k][0], afh[k][1], afh[k][2], afh[k][3], qc2, qc3);
                }
            }
            int n0 = 2 * pair * 16 + q2;        // tile0 col base
            int n1 = n0 + 16;                   // tile1 col base
            int cbase = t * CHUNK_N;
            float cs0 = s_csqr[cbase + n0], cs1 = s_csqr[cbase + n0 + 1];
            float cs2 = s_csqr[cbase + n0 + 8], cs3 = s_csqr[cbase + n0 + 9];
            float cs4 = s_csqr[cbase + n1], cs5 = s_csqr[cbase + n1 + 1];
            float cs6 = s_csqr[cbase + n1 + 8], cs7 = s_csqr[cbase + n1 + 9];

            float vA0 = fmaf(-2.f, a0, cs0),  vA1 = fmaf(-2.f, a1, cs1);
            float vA2 = fmaf(-2.f, a4, cs2),  vA3 = fmaf(-2.f, a5, cs3);
            float vA4 = fmaf(-2.f, a8, cs4),  vA5 = fmaf(-2.f, a9, cs5);
            float vA6 = fmaf(-2.f, a12, cs6), vA7 = fmaf(-2.f, a13, cs7);
            float vB0 = fmaf(-2.f, a2, cs0),  vB1 = fmaf(-2.f, a3, cs1);
            float vB2 = fmaf(-2.f, a6, cs2),  vB3 = fmaf(-2.f, a7, cs3);
            float vB4 = fmaf(-2.f, a10, cs4), vB5 = fmaf(-2.f, a11, cs5);
            float vB6 = fmaf(-2.f, a14, cs6), vB7 = fmaf(-2.f, a15, cs7);

            float mA = fminf(fminf(fminf(vA0, vA1), fminf(vA2, vA3)),
                             fminf(fminf(vA4, vA5), fminf(vA6, vA7)));
            float mB = fminf(fminf(fminf(vB0, vB1), fminf(vB2, vB3)),
                             fminf(fminf(vB4, vB5), fminf(vB6, vB7)));
            if (mA < sA3) {   // rare: full insert
                ins3(vA0, cbase + n0,     sA1, iA1, sA2, iA2, sA3, iA3);
                ins3(vA1, cbase + n0 + 1, sA1, iA1, sA2, iA2, sA3, iA3);
                ins3(vA2, cbase + n0 + 8, sA1, iA1, sA2, iA2, sA3, iA3);
                ins3(vA3, cbase + n0 + 9, sA1, iA1, sA2, iA2, sA3, iA3);
                ins3(vA4, cbase + n1,     sA1, iA1, sA2, iA2, sA3, iA3);
                ins3(vA5, cbase + n1 + 1, sA1, iA1, sA2, iA2, sA3, iA3);
                ins3(vA6, cbase + n1 + 8, sA1, iA1, sA2, iA2, sA3, iA3);
                ins3(vA7, cbase + n1 + 9, sA1, iA1, sA2, iA2, sA3, iA3);
            }
            if (mB < sB3) {
                ins3(vB0, cbase + n0,     sB1, iB1, sB2, iB2, sB3, iB3);
                ins3(vB1, cbase + n0 + 1, sB1, iB1, sB2, iB2, sB3, iB3);
                ins3(vB2, cbase + n0 + 8, sB1, iB1, sB2, iB2, sB3, iB3);
                ins3(vB3, cbase + n0 + 9, sB1, iB1, sB2, iB2, sB3, iB3);
                ins3(vB4, cbase + n1,     sB1, iB1, sB2, iB2, sB3, iB3);
                ins3(vB5, cbase + n1 + 1, sB1, iB1, sB2, iB2, sB3, iB3);
                ins3(vB6, cbase + n1 + 8, sB1, iB1, sB2, iB2, sB3, iB3);
                ins3(vB7, cbase + n1 + 9, sB1, iB1, sB2, iB2, sB3, iB3);
            }
        }
    }

    // ---- merge top-3 across the quad (lanes sharing l/4) ----
    #pragma unroll
    for (int d = 1; d <= 2; d <<= 1) {
        float t1 = __shfl_xor_sync(~0u, sA1, d); int j1 = __shfl_xor_sync(~0u, iA1, d);
        float t2 = __shfl_xor_sync(~0u, sA2, d); int j2 = __shfl_xor_sync(~0u, iA2, d);
        float t3 = __shfl_xor_sync(~0u, sA3, d); int j3 = __shfl_xor_sync(~0u, iA3, d);
        ins3(t1, j1, sA1, iA1, sA2, iA2, sA3, iA3);
        ins3(t2, j2, sA1, iA1, sA2, iA2, sA3, iA3);
        ins3(t3, j3, sA1, iA1, sA2, iA2, sA3, iA3);
        t1 = __shfl_xor_sync(~0u, sB1, d); j1 = __shfl_xor_sync(~0u, iB1, d);
        t2 = __shfl_xor_sync(~0u, sB2, d); j2 = __shfl_xor_sync(~0u, iB2, d);
        t3 = __shfl_xor_sync(~0u, sB3, d); j3 = __shfl_xor_sync(~0u, iB3, d);
        ins3(t1, j1, sB1, iB1, sB2, iB2, sB3, iB3);
        ins3(t2, j2, sB1, iB1, sB2, iB2, sB3, iB3);
        ins3(t3, j3, sB1, iB1, sB2, iB2, sB3, iB3);
    }
    if ((l & 3) == 0) {
        int rA = w * 16 + (l >> 2);
        s_ts[rA * 3 + 0] = sA1; s_ts[rA * 3 + 1] = sA2; s_ts[rA * 3 + 2] = sA3;
        s_ti[rA * 3 + 0] = iA1; s_ti[rA * 3 + 1] = iA2; s_ti[rA * 3 + 2] = iA3;
        int rB = rA + 8;
        s_ts[rB * 3 + 0] = sB1; s_ts[rB * 3 + 1] = sB2; s_ts[rB * 3 + 2] = sB3;
        s_ti[rB * 3 + 0] = iB1; s_ti[rB * 3 + 1] = iB2; s_ti[rB * 3 + 2] = iB3;
    }
    __syncthreads();

    // ---- per-row rescue + outputs (threads 0..127, one row each) ----
    float err = 0.0f;
    if (tid < ROWS_PER_CTA) {
        int row = row0 + tid;
        const float4* x4 = (const float4*)(inp + (size_t)row * D);
        float s1 = s_ts[tid * 3], s2 = s_ts[tid * 3 + 1], s3 = s_ts[tid * 3 + 2];
        int i1 = s_ti[tid * 3], i2 = s_ti[tid * 3 + 1], i3 = s_ti[tid * 3 + 2];
        int bidx = i1;
        if (s2 < s1 + MARGIN) {
            float e1 = exact_score(x4, codebook, i1);
            float e2 = exact_score(x4, codebook, i2);
            float eb = e1; bidx = i1;
            if (e2 < eb || (e2 == eb && i2 < bidx)) { eb = e2; bidx = i2; }
            if (s3 < s1 + MARGIN) {
                float e3 = exact_score(x4, codebook, i3);
                if (e3 < eb || (e3 == eb && i3 < bidx)) { eb = e3; bidx = i3; }
            }
        }
        float q[D];
        const float4* q4 = (const float4*)(codebook + (size_t)bidx * D);
        #pragma unroll
        for (int i = 0; i < 16; i++) {
            float4 qq = q4[i];
            float4 x = x4[i];
            q[4 * i + 0] = qq.x; q[4 * i + 1] = qq.y;
            q[4 * i + 2] = qq.z; q[4 * i + 3] = qq.w;
            float dx = x.x - qq.x, dy = x.y - qq.y;
            float dz = x.z - qq.z, dw = x.w - qq.w;
            err += dx * dx + dy * dy + dz * dz + dw * dw;
        }
        // z_q at out+1 (4B offset): i=0,1,2,63 scalar; i=3..62 aligned float4
        float* orow = out + 1 + (size_t)row * D;
        orow[0] = q[0]; orow[1] = q[1]; orow[2] = q[2];
        #pragma unroll
        for (int b = 0; b < 15; b++) {
            int i = 3 + 4 * b;
            *(float4*)(orow + i) = make_float4(q[i], q[i + 1], q[i + 2], q[i + 3]);
        }
        orow[63] = q[63];
        out[1 + (size_t)n_rows * D + row] = (float)bidx;
    }
    #pragma unroll
    for (int off = 16; off > 0; off >>= 1)
        err += __shfl_down_sync(0xffffffffu, err, off);
    if ((tid & 31) == 0 && err != 0.0f)
        atomicAdd(&g_loss_accum, (double)err);

    // ---- last CTA finalizes loss ----
    __syncthreads();
    if (tid == 0) {
        __threadfence();
        unsigned tkt = atomicAdd(&g_ticket, 1u);
        if (tkt == gridDim.x - 1) {
            __threadfence();
            double L = g_loss_accum;
            out[0] = (float)(L * (1.25 / ((double)n_rows * (double)D)));
            g_loss_accum = 0.0;
            g_ticket = 0u;
        }
    }
}

extern "C" void kernel_launch(void* const* d_in, const int* in_sizes, int n_in,
                              void* d_out, int out_size) {
    const float* inp = (const float*)d_in[0];
    const float* codebook = (const float*)d_in[1];
    float* out = (float*)d_out;
    const int n_rows = in_sizes[0] / D;   // 131072

    static bool attr_done = false;
    if (!attr_done) {
        cudaFuncSetAttribute(vq_main_kernel,
                             cudaFuncAttributeMaxDynamicSharedMemorySize,
                             SMEM_TOTAL);
        attr_done = true;
    }
    vq_prep_kernel<<<(KCODES + 255) / 256, 256>>>(codebook);
    vq_main_kernel<<<n_rows / ROWS_PER_CTA, TPB, SMEM_TOTAL>>>(inp, codebook,
                                                               out, n_rows);
    (void)n_in; (void)out_size;
}

// round 17
// speedup vs baseline: 1.8715x; 1.8715x over previous
#include <cuda_runtime.h>
#include <cuda_bf16.h>
#include <cstdint>

// QuantizedCodebook: inputs [32,4096,64] f32, codebook [1024,64] f32.
// Output (f32 concat): [ loss(1) | z_q(N*64) | indices-as-f32(N) ]
//
// R17 = R15 (best, 236us; occ3/regs80) with the k-step reordered for 4-way
// accumulator-chain rotation: ldsm ch(t0,t1) -> 4x afh*ch (4 chains) ->
// ldsm cl(t0,t1) (hidden under MMAs) -> 4x afl*ch -> 4x afh*cl.
// Chain RAW spacing 1 -> 4 MMAs. Math identical: bf16 split B'=[ch|cl],
// |err|~1e-4; top-3 + exact fp32 rescore within MARGIN; exact z_q/loss.

#define D 64
#define KCODES 1024
#define TPB 256
#define ROWS_PER_CTA 128
#define CHUNK_N 64
#define NCHUNKS (KCODES / CHUNK_N)       // 16
#define NK 4                             // 4 k16-steps per 64-dim plane
#define RSA 272                          // A row: [xh 128B | xl 128B] + 16 pad
#define RSB 272                          // B row: [ch 128B | cl 128B] + 16 pad
#define MARGIN 2e-3f

// dynamic smem layout (A-stage overlaps B0+B1 exactly: 128*272 = 34816)
#define SM_B0 0                          // 64*272 = 17408
#define SM_B1 17408
#define SM_CS 34816                      // csqr[1024] (4096)
#define SM_TS 38912                      // float top3 s [128][3] (1536)
#define SM_TI 40448                      // int   top3 i [128][3] (1536)
#define SMEM_TOTAL 41984

__device__ double g_loss_accum;
__device__ unsigned int g_ticket;
__device__ float g_csqr[KCODES];
__device__ unsigned int g_cbq[KCODES * 64];   // per code: [ch 32 u32 | cl 32 u32]

// ---------------- helpers ----------------
__device__ __forceinline__ uint32_t smem_u32(const void* p) {
    uint32_t a;
    asm("{ .reg .u64 t; cvta.to.shared.u64 t, %1; cvt.u32.u64 %0, t; }"
        : "=r"(a) : "l"(p));
    return a;
}
__device__ __forceinline__ uint32_t packbf(float a, float b) {
    uint32_t r;
    asm("cvt.rn.bf16x2.f32 %0, %1, %2;" : "=r"(r) : "f"(b), "f"(a));
    return r;
}
__device__ __forceinline__ float lo_f(uint32_t p) { return __uint_as_float(p << 16); }
__device__ __forceinline__ float hi_f(uint32_t p) { return __uint_as_float(p & 0xffff0000u); }

__device__ __forceinline__ void ldsm4(uint32_t& r0, uint32_t& r1,
                                      uint32_t& r2, uint32_t& r3, uint32_t a) {
    asm volatile("ldmatrix.sync.aligned.m8n8.x4.shared.b16 {%0,%1,%2,%3}, [%4];"
                 : "=r"(r0), "=r"(r1), "=r"(r2), "=r"(r3) : "r"(a));
}
__device__ __forceinline__ void mma16816(float& c0, float& c1, float& c2, float& c3,
                                         uint32_t a0, uint32_t a1, uint32_t a2,
                                         uint32_t a3, uint32_t b0, uint32_t b1) {
    asm("mma.sync.aligned.m16n8k16.row.col.f32.bf16.bf16.f32 "
        "{%0,%1,%2,%3}, {%4,%5,%6,%7}, {%8,%9}, {%0,%1,%2,%3};"
        : "+f"(c0), "+f"(c1), "+f"(c2), "+f"(c3)
        : "r"(a0), "r"(a1), "r"(a2), "r"(a3), "r"(b0), "r"(b1));
}
__device__ __forceinline__ void cpa16(uint32_t dst, const void* src) {
    asm volatile("cp.async.cg.shared.global [%0], [%1], 16;"
                 :: "r"(dst), "l"(src));
}
#define CP_COMMIT() asm volatile("cp.async.commit_group;" ::: "memory")
#define CP_WAIT0()  asm volatile("cp.async.wait_group 0;" ::: "memory")

__device__ __forceinline__ void ins3(float s, int idx,
                                     float& s1, int& i1, float& s2, int& i2,
                                     float& s3, int& i3) {
    if (s < s3) {
        if (s < s2) {
            if (s < s1) { s3 = s2; i3 = i2; s2 = s1; i2 = i1; s1 = s; i1 = idx; }
            else        { s3 = s2; i3 = i2; s2 = s;  i2 = idx; }
        } else { s3 = s; i3 = idx; }
    }
}

// ---------------- kernel 1: prep (split codebook + norms) ----------------
__global__ void vq_prep_kernel(const float* __restrict__ codebook) {
    int j = blockIdx.x * blockDim.x + threadIdx.x;
    if (j == 0) { g_loss_accum = 0.0; g_ticket = 0u; }
    if (j >= KCODES) return;
    const float4* c4 = (const float4*)(codebook + (size_t)j * D);
    unsigned int* q = g_cbq + (size_t)j * 64;
    float s = 0.0f;
    #pragma unroll
    for (int i = 0; i < 16; i++) {
        float4 v = c4[i];
        s += v.x * v.x + v.y * v.y + v.z * v.z + v.w * v.w;
        uint32_t h0 = packbf(v.x, v.y), h1 = packbf(v.z, v.w);
        uint32_t l0 = packbf(v.x - lo_f(h0), v.y - hi_f(h0));
        uint32_t l1 = packbf(v.z - lo_f(h1), v.w - hi_f(h1));
        q[2 * i] = h0;       q[2 * i + 1] = h1;        // ch plane
        q[32 + 2 * i] = l0;  q[32 + 2 * i + 1] = l1;   // cl plane
    }
    g_csqr[j] = s;
}

__device__ __forceinline__ float exact_score(const float4* x4,
                                             const float* __restrict__ cb, int j) {
    const float4* c4 = (const float4*)(cb + (size_t)j * D);
    float dot = 0.0f;
    #pragma unroll
    for (int i = 0; i < 16; i++) {
        float4 a = x4[i], b = c4[i];
        dot += a.x * b.x + a.y * b.y + a.z * b.z + a.w * b.w;
    }
    return fmaf(-2.0f, dot, g_csqr[j]);
}

// ---------------- kernel 2: main ----------------
__global__ void __launch_bounds__(TPB, 3)
vq_main_kernel(const float* __restrict__ inp,
               const float* __restrict__ codebook,
               float* __restrict__ out, int n_rows) {
    extern __shared__ char dsm[];
    const uint32_t sbase = smem_u32(dsm);
    float* s_csqr = (float*)(dsm + SM_CS);
    float* s_ts = (float*)(dsm + SM_TS);
    int*   s_ti = (int*)(dsm + SM_TI);

    const int tid = threadIdx.x;
    const int l = tid & 31;
    const int w = tid >> 5;
    const int row0 = blockIdx.x * ROWS_PER_CTA;

    // ---- stage A [128 rows][xh|xl] bf16 stride 272 (overlaps B0+B1) ----
    if (tid < ROWS_PER_CTA) {
        const float4* xr = (const float4*)(inp + (size_t)(row0 + tid) * D);
        uint32_t* arow = (uint32_t*)(dsm + tid * RSA);
        #pragma unroll
        for (int i = 0; i < 16; i++) {
            float4 v = xr[i];
            uint32_t h0 = packbf(v.x, v.y), h1 = packbf(v.z, v.w);
            uint32_t l0 = packbf(v.x - lo_f(h0), v.y - hi_f(h0));
            uint32_t l1 = packbf(v.z - lo_f(h1), v.w - hi_f(h1));
            arow[2 * i] = h0;       arow[2 * i + 1] = h1;       // xh
            arow[32 + 2 * i] = l0;  arow[32 + 2 * i + 1] = l1;  // xl
        }
    }
    for (int g = tid; g < KCODES; g += TPB) s_csqr[g] = g_csqr[g];
    __syncthreads();

    // ---- preload A fragments (held all kernel): 4 k-steps x (hi, lo) ----
    uint32_t afh[NK][4], afl[NK][4];
    {
        uint32_t aoff = (uint32_t)((w * 16 + (l & 15)) * RSA + ((l & 16) ? 16 : 0));
        #pragma unroll
        for (int k = 0; k < NK; k++) {
            ldsm4(afh[k][0], afh[k][1], afh[k][2], afh[k][3], sbase + aoff + k * 32);
            ldsm4(afl[k][0], afl[k][1], afl[k][2], afl[k][3],
                  sbase + aoff + 128 + k * 32);
        }
    }
    __syncthreads();   // all A reads done before B overwrites the buffer

    float sA1 = 3.4e38f, sA2 = 3.4e38f, sA3 = 3.4e38f;
    float sB1 = 3.4e38f, sB2 = 3.4e38f, sB3 = 3.4e38f;
    int iA1 = 0, iA2 = 0, iA3 = 0, iB1 = 0, iB2 = 0, iB3 = 0;

    const uint32_t boff = (uint32_t)(((l & 7) + ((l & 16) ? 8 : 0)) * RSB
                                     + ((l & 8) ? 16 : 0));
    const int q2 = 2 * (l & 3);
    const uint4* cbq4 = (const uint4*)g_cbq;
    const uint32_t bb[2] = { sbase + SM_B0, sbase + SM_B1 };

    // staging: thread t stages row t>>2, uint4 cols (t&3)*4 .. +3
    const int st_row = tid >> 2;              // 0..63
    const int st_c0 = (tid & 3) * 4;          // 0,4,8,12

    // prefetch chunk 0: 64 codes x 256B = 1024 x 16B (4 per thread)
    {
        const uint4* src = cbq4 + (size_t)st_row * 16 + st_c0;
        uint32_t dst = bb[0] + (uint32_t)(st_row * RSB + st_c0 * 16);
        #pragma unroll
        for (int i = 0; i < 4; i++) cpa16(dst + i * 16, src + i);
        CP_COMMIT();
    }

    for (int t = 0; t < NCHUNKS; t++) {
        CP_WAIT0();
        __syncthreads();   // chunk t visible; all reads of other buf done
        if (t + 1 < NCHUNKS) {
            const uint4* src = cbq4 + (size_t)(t + 1) * CHUNK_N * 16
                             + (size_t)st_row * 16 + st_c0;
            uint32_t dst = bb[(t + 1) & 1]
                         + (uint32_t)(st_row * RSB + st_c0 * 16);
            #pragma unroll
            for (int i = 0; i < 4; i++) cpa16(dst + i * 16, src + i);
            CP_COMMIT();
        }
        const uint32_t bch = bb[t & 1];

        #pragma unroll
        for (int pair = 0; pair < 2; pair++) {
            // 2 n16 tiles (32 codes); 4 dst chains, round-robin rotation
            float a0 = 0.f, a1 = 0.f, a2 = 0.f, a3 = 0.f;       // tile0 n8-lo
            float a4 = 0.f, a5 = 0.f, a6 = 0.f, a7 = 0.f;       // tile0 n8-hi
            float a8 = 0.f, a9 = 0.f, a10 = 0.f, a11 = 0.f;     // tile1 n8-lo
            float a12 = 0.f, a13 = 0.f, a14 = 0.f, a15 = 0.f;   // tile1 n8-hi
            uint32_t b0base = bch + (uint32_t)((2 * pair) * 16 * RSB) + boff;
            uint32_t b1base = b0base + (uint32_t)(16 * RSB);
            #pragma unroll
            for (int k = 0; k < NK; k++) {
                uint32_t p0, p1, p2, p3, q0, q1, q2r, q3;
                uint32_t pc0, pc1, pc2, pc3, qc0, qc1, qc2, qc3;
                // ch frags for both tiles first
                ldsm4(p0, p1, p2, p3, b0base + k * 32);           // t0 ch
                ldsm4(q0, q1, q2r, q3, b1base + k * 32);          // t1 ch
                // round 1: afh*ch across all 4 chains
                mma16816(a0, a1, a2, a3, afh[k][0], afh[k][1], afh[k][2], afh[k][3], p0, p1);
                mma16816(a4, a5, a6, a7, afh[k][0], afh[k][1], afh[k][2], afh[k][3], p2, p3);
                mma16816(a8, a9, a10, a11, afh[k][0], afh[k][1], afh[k][2], afh[k][3], q0, q1);
                mma16816(a12, a13, a14, a15, afh[k][0], afh[k][1], afh[k][2], afh[k][3], q2r, q3);
                // cl frags issue while round-1 MMAs drain
                ldsm4(pc0, pc1, pc2, pc3, b0base + 128 + k * 32); // t0 cl
                ldsm4(qc0, qc1, qc2, qc3, b1base + 128 + k * 32); // t1 cl
                // round 2: afl*ch
                mma16816(a0, a1, a2, a3, afl[k][0], afl[k][1], afl[k][2], afl[k][3], p0, p1);
                mma16816(a4, a5, a6, a7, afl[k][0], afl[k][1], afl[k][2], afl[k][3], p2, p3);
                mma16816(a8, a9, a10, a11, afl[k][0], afl[k][1], afl[k][2], afl[k][3], q0, q1);
                mma16816(a12, a13, a14, a15, afl[k][0], afl[k][1], afl[k][2], afl[k][3], q2r, q3);
                // round 3: afh*cl
                mma16816(a0, a1, a2, a3, afh[k][0], afh[k][1], afh[k][2], afh[k][3], pc0, pc1);
                mma16816(a4, a5, a6, a7, afh[k][0], afh[k][1], afh[k][2], afh[k][3], pc2, pc3);
                mma16816(a8, a9, a10, a11, afh[k][0], afh[k][1], afh[k][2], afh[k][3], qc0, qc1);
                mma16816(a12, a13, a14, a15, afh[k][0], afh[k][1], afh[k][2], afh[k][3], qc2, qc3);
            }
            int n0 = 2 * pair * 16 + q2;        // tile0 col base
            int n1 = n0 + 16;                   // tile1 col base
            int cbase = t * CHUNK_N;
            float cs0 = s_csqr[cbase + n0], cs1 = s_csqr[cbase + n0 + 1];
            float cs2 = s_csqr[cbase + n0 + 8], cs3 = s_csqr[cbase + n0 + 9];
            float cs4 = s_csqr[cbase + n1], cs5 = s_csqr[cbase + n1 + 1];
            float cs6 = s_csqr[cbase + n1 + 8], cs7 = s_csqr[cbase + n1 + 9];

            float vA0 = fmaf(-2.f, a0, cs0),  vA1 = fmaf(-2.f, a1, cs1);
            float vA2 = fmaf(-2.f, a4, cs2),  vA3 = fmaf(-2.f, a5, cs3);
            float vA4 = fmaf(-2.f, a8, cs4),  vA5 = fmaf(-2.f, a9, cs5);
            float vA6 = fmaf(-2.f, a12, cs6), vA7 = fmaf(-2.f, a13, cs7);
            float vB0 = fmaf(-2.f, a2, cs0),  vB1 = fmaf(-2.f, a3, cs1);
            float vB2 = fmaf(-2.f, a6, cs2),  vB3 = fmaf(-2.f, a7, cs3);
            float vB4 = fmaf(-2.f, a10, cs4), vB5 = fmaf(-2.f, a11, cs5);
            float vB6 = fmaf(-2.f, a14, cs6), vB7 = fmaf(-2.f, a15, cs7);

            float mA = fminf(fminf(fminf(vA0, vA1), fminf(vA2, vA3)),
                             fminf(fminf(vA4, vA5), fminf(vA6, vA7)));
            float mB = fminf(fminf(fminf(vB0, vB1), fminf(vB2, vB3)),
                             fminf(fminf(vB4, vB5), fminf(vB6, vB7)));
            if (mA < sA3) {   // rare: full insert
                ins3(vA0, cbase + n0,     sA1, iA1, sA2, iA2, sA3, iA3);
                ins3(vA1, cbase + n0 + 1, sA1, iA1, sA2, iA2, sA3, iA3);
                ins3(vA2, cbase + n0 + 8, sA1, iA1, sA2, iA2, sA3, iA3);
                ins3(vA3, cbase + n0 + 9, sA1, iA1, sA2, iA2, sA3, iA3);
                ins3(vA4, cbase + n1,     sA1, iA1, sA2, iA2, sA3, iA3);
                ins3(vA5, cbase + n1 + 1, sA1, iA1, sA2, iA2, sA3, iA3);
                ins3(vA6, cbase + n1 + 8, sA1, iA1, sA2, iA2, sA3, iA3);
                ins3(vA7, cbase + n1 + 9, sA1, iA1, sA2, iA2, sA3, iA3);
            }
            if (mB < sB3) {
                ins3(vB0, cbase + n0,     sB1, iB1, sB2, iB2, sB3, iB3);
                ins3(vB1, cbase + n0 + 1, sB1, iB1, sB2, iB2, sB3, iB3);
                ins3(vB2, cbase + n0 + 8, sB1, iB1, sB2, iB2, sB3, iB3);
                ins3(vB3, cbase + n0 + 9, sB1, iB1, sB2, iB2, sB3, iB3);
                ins3(vB4, cbase + n1,     sB1, iB1, sB2, iB2, sB3, iB3);
                ins3(vB5, cbase + n1 + 1, sB1, iB1, sB2, iB2, sB3, iB3);
                ins3(vB6, cbase + n1 + 8, sB1, iB1, sB2, iB2, sB3, iB3);
                ins3(vB7, cbase + n1 + 9, sB1, iB1, sB2, iB2, sB3, iB3);
            }
        }
    }

    // ---- merge top-3 across the quad (lanes sharing l/4) ----
    #pragma unroll
    for (int d = 1; d <= 2; d <<= 1) {
        float t1 = __shfl_xor_sync(~0u, sA1, d); int j1 = __shfl_xor_sync(~0u, iA1, d);
        float t2 = __shfl_xor_sync(~0u, sA2, d); int j2 = __shfl_xor_sync(~0u, iA2, d);
        float t3 = __shfl_xor_sync(~0u, sA3, d); int j3 = __shfl_xor_sync(~0u, iA3, d);
        ins3(t1, j1, sA1, iA1, sA2, iA2, sA3, iA3);
        ins3(t2, j2, sA1, iA1, sA2, iA2, sA3, iA3);
        ins3(t3, j3, sA1, iA1, sA2, iA2, sA3, iA3);
        t1 = __shfl_xor_sync(~0u, sB1, d); j1 = __shfl_xor_sync(~0u, iB1, d);
        t2 = __shfl_xor_sync(~0u, sB2, d); j2 = __shfl_xor_sync(~0u, iB2, d);
        t3 = __shfl_xor_sync(~0u, sB3, d); j3 = __shfl_xor_sync(~0u, iB3, d);
        ins3(t1, j1, sB1, iB1, sB2, iB2, sB3, iB3);
        ins3(t2, j2, sB1, iB1, sB2, iB2, sB3, iB3);
        ins3(t3, j3, sB1, iB1, sB2, iB2, sB3, iB3);
    }
    if ((l & 3) == 0) {
        int rA = w * 16 + (l >> 2);
        s_ts[rA * 3 + 0] = sA1; s_ts[rA * 3 + 1] = sA2; s_ts[rA * 3 + 2] = sA3;
        s_ti[rA * 3 + 0] = iA1; s_ti[rA * 3 + 1] = iA2; s_ti[rA * 3 + 2] = iA3;
        int rB = rA + 8;
        s_ts[rB * 3 + 0] = sB1; s_ts[rB * 3 + 1] = sB2; s_ts[rB * 3 + 2] = sB3;
        s_ti[rB * 3 + 0] = iB1; s_ti[rB * 3 + 1] = iB2; s_ti[rB * 3 + 2] = iB3;
    }
    __syncthreads();

    // ---- per-row rescue + outputs (threads 0..127, one row each) ----
    float err = 0.0f;
    if (tid < ROWS_PER_CTA) {
        int row = row0 + tid;
        const float4* x4 = (const float4*)(inp + (size_t)row * D);
        float s1 = s_ts[tid * 3], s2 = s_ts[tid * 3 + 1], s3 = s_ts[tid * 3 + 2];
        int i1 = s_ti[tid * 3], i2 = s_ti[tid * 3 + 1], i3 = s_ti[tid * 3 + 2];
        int bidx = i1;
        if (s2 < s1 + MARGIN) {
            float e1 = exact_score(x4, codebook, i1);
            float e2 = exact_score(x4, codebook, i2);
            float eb = e1; bidx = i1;
            if (e2 < eb || (e2 == eb && i2 < bidx)) { eb = e2; bidx = i2; }
            if (s3 < s1 + MARGIN) {
                float e3 = exact_score(x4, codebook, i3);
                if (e3 < eb || (e3 == eb && i3 < bidx)) { eb = e3; bidx = i3; }
            }
        }
        float q[D];
        const float4* q4 = (const float4*)(codebook + (size_t)bidx * D);
        #pragma unroll
        for (int i = 0; i < 16; i++) {
            float4 qq = q4[i];
            float4 x = x4[i];
            q[4 * i + 0] = qq.x; q[4 * i + 1] = qq.y;
            q[4 * i + 2] = qq.z; q[4 * i + 3] = qq.w;
            float dx = x.x - qq.x, dy = x.y - qq.y;
            float dz = x.z - qq.z, dw = x.w - qq.w;
            err += dx * dx + dy * dy + dz * dz + dw * dw;
        }
        // z_q at out+1 (4B offset): i=0,1,2,63 scalar; i=3..62 aligned float4
        float* orow = out + 1 + (size_t)row * D;
        orow[0] = q[0]; orow[1] = q[1]; orow[2] = q[2];
        #pragma unroll
        for (int b = 0; b < 15; b++) {
            int i = 3 + 4 * b;
            *(float4*)(orow + i) = make_float4(q[i], q[i + 1], q[i + 2], q[i + 3]);
        }
        orow[63] = q[63];
        out[1 + (size_t)n_rows * D + row] = (float)bidx;
    }
    #pragma unroll
    for (int off = 16; off > 0; off >>= 1)
        err += __shfl_down_sync(0xffffffffu, err, off);
    if ((tid & 31) == 0 && err != 0.0f)
        atomicAdd(&g_loss_accum, (double)err);

    // ---- last CTA finalizes loss ----
    __syncthreads();
    if (tid == 0) {
        __threadfence();
        unsigned tkt = atomicAdd(&g_ticket, 1u);
        if (tkt == gridDim.x - 1) {
            __threadfence();
            double L = g_loss_accum;
            out[0] = (float)(L * (1.25 / ((double)n_rows * (double)D)));
            g_loss_accum = 0.0;
            g_ticket = 0u;
        }
    }
}

extern "C" void kernel_launch(void* const* d_in, const int* in_sizes, int n_in,
                              void* d_out, int out_size) {
    const float* inp = (const float*)d_in[0];
    const float* codebook = (const float*)d_in[1];
    float* out = (float*)d_out;
    const int n_rows = in_sizes[0] / D;   // 131072

    static bool attr_done = false;
    if (!attr_done) {
        cudaFuncSetAttribute(vq_main_kernel,
                             cudaFuncAttributeMaxDynamicSharedMemorySize,
                             SMEM_TOTAL);
        attr_done = true;
    }
    vq_prep_kernel<<<(KCODES + 255) / 256, 256>>>(codebook);
    vq_main_kernel<<<n_rows / ROWS_PER_CTA, TPB, SMEM_TOTAL>>>(inp, codebook,
                                                               out, n_rows);
    (void)n_in; (void)out_size;
}